// round 7
// baseline (speedup 1.0000x reference)
#include <cuda_runtime.h>

// PercolationQ: per-patch occupancy fraction -> threshold -> mean over patches.
// Pure HBM-bound streaming reduction over three 50 MB fp32 tensors.
//
// Layout (flat view):
//   x4 : [3,64,4096,4,4]   patch = 16 floats  = 4  float4
//   x8 : [3,64,1024,8,8]   patch = 64 floats  = 16 float4
//   x16: [3,64, 256,16,16] patch = 256 floats = 64 float4
// Output: [q4(3,64), q8(3,64), q16(3,64)] = 576 floats.
//
// R6: SINGLE-WAVE grid. 1152 blocks x 256 threads (all co-resident at occ 8):
// each block streams two 64 KB chunks (bid, bid+1152) -> no wave transition.
// Per chunk: coalesced warp loads (512 B per LDG.128, evict-first __ldcs),
// per-float4 partials staged to swizzled smem, then uniform gather/threshold.
// Last block finalizes in-kernel (ticket pattern) -- single graph node.

#define PERC_THR 0.59275f
#define NBLK 1152
#define NCHUNK 2304

__device__ int g_part[NCHUNK];          // per-chunk patch counts
__device__ unsigned int g_ticket = 0;   // self-resetting -> deterministic replays

__device__ __forceinline__ float red4(float4 a) {
    return (a.x + a.y) + (a.z + a.w);
}

__device__ __forceinline__ int swz(int g) {   // group swizzle (conflict-free)
    return g ^ ((g >> 3) & 7);
}

__device__ __forceinline__ float4 ldcs4(const float4* p) {
    return __ldcs(p);
}

// Returns valid total only on threadIdx.x == 0.
__device__ __forceinline__ int block_reduce_count(int c, int* sh) {
    c = __reduce_add_sync(0xffffffffu, c);
    int warp = threadIdx.x >> 5;
    if ((threadIdx.x & 31) == 0) sh[warp] = c;
    __syncthreads();
    if (threadIdx.x == 0) {
        int s = 0;
#pragma unroll
        for (int i = 0; i < 8; i++) s += sh[i];
        return s;
    }
    return 0;
}

__global__ void __launch_bounds__(256)
perc_kernel(const float* __restrict__ x4,
            const float* __restrict__ x8,
            const float* __restrict__ x16,
            float* __restrict__ out) {
    __shared__ float s_part[4096];      // 16 KB: one partial per float4, swizzled
    __shared__ int sh[8];
    __shared__ bool sh_last;

    const int bid  = blockIdx.x;
    const int tid  = threadIdx.x;
    const int warp = tid >> 5;
    const int lane = tid & 31;

    const int gwarp = warp * 128;
    const int gsub  = lane >> 4;        // unused placeholder (kept simple below)
    (void)gsub;

#pragma unroll
    for (int half = 0; half < 2; half++) {
        const int chunk = bid + half * NBLK;   // 0..2303

        const float4* seg;
        if (chunk < 768)
            seg = (const float4*)x4 + (size_t)chunk * 4096;
        else if (chunk < 1536)
            seg = (const float4*)x8 + (size_t)(chunk - 768) * 4096;
        else
            seg = (const float4*)x16 + (size_t)(chunk - 1536) * 4096;
        seg += warp * 512;

        // ---- Phase 1: coalesced stream, per-float4 partials -> swizzled smem
        const int gs   = lane >> 2;     // sub-group within warp iteration
        const int comp = lane & 3;
#pragma unroll
        for (int io = 0; io < 16; io += 4) {
            float4 v0 = ldcs4(seg + (io + 0) * 32 + lane);
            float4 v1 = ldcs4(seg + (io + 1) * 32 + lane);
            float4 v2 = ldcs4(seg + (io + 2) * 32 + lane);
            float4 v3 = ldcs4(seg + (io + 3) * 32 + lane);
            s_part[4 * swz(gwarp + (io + 0) * 8 + gs) + comp] = red4(v0);
            s_part[4 * swz(gwarp + (io + 1) * 8 + gs) + comp] = red4(v1);
            s_part[4 * swz(gwarp + (io + 2) * 8 + gs) + comp] = red4(v2);
            s_part[4 * swz(gwarp + (io + 3) * 8 + gs) + comp] = red4(v3);
        }
        __syncthreads();

        // ---- Phase 2: gather 4 float4-of-partials per thread (groups 4t..4t+3)
        const float4* sp4 = (const float4*)s_part;
        float4 p0 = sp4[swz(4 * tid + 0)];
        float4 p1 = sp4[swz(4 * tid + 1)];
        float4 p2 = sp4[swz(4 * tid + 2)];
        float4 p3 = sp4[swz(4 * tid + 3)];

        int cnt = 0;
        if (chunk < 768) {
            // x4: each float4-of-partials is one whole patch (4 patches/thread)
            cnt += (red4(p0) * 0.0625f >= PERC_THR) ? 1 : 0;
            cnt += (red4(p1) * 0.0625f >= PERC_THR) ? 1 : 0;
            cnt += (red4(p2) * 0.0625f >= PERC_THR) ? 1 : 0;
            cnt += (red4(p3) * 0.0625f >= PERC_THR) ? 1 : 0;
        } else if (chunk < 1536) {
            // x8: all 16 partials form one patch
            float s = (red4(p0) + red4(p1)) + (red4(p2) + red4(p3));
            cnt = (s * 0.015625f >= PERC_THR) ? 1 : 0;
        } else {
            // x16: 4 threads per patch, combine with 2 shfls
            float s = (red4(p0) + red4(p1)) + (red4(p2) + red4(p3));
            s += __shfl_xor_sync(0xffffffffu, s, 1);
            s += __shfl_xor_sync(0xffffffffu, s, 2);
            cnt = ((tid & 3) == 0 && (s * 0.00390625f >= PERC_THR)) ? 1 : 0;
        }

        int total = block_reduce_count(cnt, sh);
        if (tid == 0) g_part[chunk] = total;
        __syncthreads();   // protect sh[] and s_part[] before next chunk
    }

    // ---- last-block finalize (threadfence-reduction pattern) ----
    if (tid == 0) {
        __threadfence();                       // publish g_part writes
        unsigned int t = atomicAdd(&g_ticket, 1);
        sh_last = (t == NBLK - 1);
    }
    __syncthreads();
    if (sh_last) {
        for (int t = tid; t < 576; t += 256) {
            const int tensor = t / 192;        // 0: x4, 1: x8, 2: x16
            const int row = t % 192;
            const int* part = g_part + tensor * 768 + row * 4;
            int c = part[0] + part[1] + part[2] + part[3];
            const float invP = (tensor == 0) ? (1.0f / 4096.0f)
                             : (tensor == 1) ? (1.0f / 1024.0f)
                                             : (1.0f / 256.0f);
            out[t] = (float)c * invP;
        }
        if (tid == 0) g_ticket = 0;            // reset for next graph replay
    }
}

extern "C" void kernel_launch(void* const* d_in, const int* in_sizes, int n_in,
                              void* d_out, int out_size) {
    const float* x4  = (const float*)d_in[0];
    const float* x8  = (const float*)d_in[1];
    const float* x16 = (const float*)d_in[2];
    float* out = (float*)d_out;

    perc_kernel<<<NBLK, 256>>>(x4, x8, x16, out);
}